// round 16
// baseline (speedup 1.0000x reference)
#include <cuda_runtime.h>
#include <cuda_fp16.h>
#include <math.h>

// Problem constants
constexpr int N_B   = 4;
constexpr int SEQ_T = 2048;
constexpr int N_P   = 16;
constexpr int JD    = 256;
constexpr int NH    = 4;
constexpr int DH    = 16;
constexpr int MEMD  = 64;
constexpr int KOUT  = 192;
constexpr int NSEQ  = N_B * N_P;        // 64
constexpr int NT    = NSEQ * SEQ_T;     // 131072 tokens
constexpr float EPS_LN = 1e-5f;

// chunked-scan constants
constexpr int CH   = 128;
constexpr int NCH  = SEQ_T / CH;        // 16
constexpr int NREC = NSEQ * NH;         // 256
constexpr int NGRP = NREC * NCH;        // 4096

// GEMM constants
constexpr int ABS = 20;                     // padded word stride for smem rows
constexpr int A_BUF_W = 64 * ABS;           // words per A buffer = 1280
constexpr int B_BUF_W = 128 * ABS;          // words per B buffer = 2560
// staging: 3*A + 3*B = 11520 words = 46080 B; aliased C tile = 33792 B. staging dominates.
constexpr int GEMM_SMEM = 3 * (A_BUF_W + B_BUF_W) * 4;   // 46080
constexpr float WSCALE = 16384.0f;          // 2^14 pre-scale (fp16 subnormal guard)
constexpr float DESC   = 1.0f / 16384.0f;

// final_proj constants
constexpr int FP_TT   = 64;
constexpr int FP_SOW  = 66;
constexpr int FP_SMEM = (64 * 192 + 64 * FP_SOW) * 4;   // 66048 B

// ---------------- scratch (device globals; allocation-free) ----------------
__device__ unsigned int g_wh[256 * 128];     // W fp16 pairs (scaled), [n][c]
__device__ float g_wtr[MEMD * KOUT];
__device__ float g_q[(size_t)NREC * SEQ_T * DH];
__device__ float g_k[(size_t)NREC * SEQ_T * DH];
__device__ float g_v[(size_t)NREC * SEQ_T * DH];
__device__ float g_o[(size_t)NREC * SEQ_T * DH];
__device__ float g_beta[NREC * SEQ_T];
__device__ float g_alpha[NREC * SEQ_T];
__device__ float g_P[(size_t)NGRP * 256];
__device__ float g_R[(size_t)NGRP * 256];
__device__ float g_S[(size_t)NGRP * 256];

// ---------------- f32x2 helpers ----------------
__device__ __forceinline__ unsigned long long dup2(float x) {
    unsigned long long r;
    unsigned int xi = __float_as_uint(x);
    asm("mov.b64 %0, {%1, %1};" : "=l"(r) : "r"(xi));
    return r;
}
__device__ __forceinline__ unsigned long long pack2(float lo, float hi) {
    unsigned long long r;
    asm("mov.b64 %0, {%1, %2};" : "=l"(r) : "f"(lo), "f"(hi));
    return r;
}
__device__ __forceinline__ void fma2(unsigned long long& acc, unsigned long long a,
                                     unsigned long long b) {
    asm("fma.rn.f32x2 %0, %1, %2, %0;" : "+l"(acc) : "l"(a), "l"(b));
}
__device__ __forceinline__ unsigned long long mul2(unsigned long long a, unsigned long long b) {
    unsigned long long r;
    asm("mul.rn.f32x2 %0, %1, %2;" : "=l"(r) : "l"(a), "l"(b));
    return r;
}
__device__ __forceinline__ unsigned long long add2(unsigned long long a, unsigned long long b) {
    unsigned long long r;
    asm("add.rn.f32x2 %0, %1, %2;" : "=l"(r) : "l"(a), "l"(b));
    return r;
}
__device__ __forceinline__ float lo32(unsigned long long v) {
    return __uint_as_float((unsigned int)(v & 0xffffffffull));
}
__device__ __forceinline__ float hi32(unsigned long long v) {
    return __uint_as_float((unsigned int)(v >> 32));
}
__device__ __forceinline__ float dot16(const unsigned long long* A, const unsigned long long* k) {
    unsigned long long c0 = mul2(A[0], k[0]);
    unsigned long long c1 = mul2(A[1], k[1]);
    unsigned long long c2 = mul2(A[2], k[2]);
    unsigned long long c3 = mul2(A[3], k[3]);
    fma2(c0, A[4], k[4]);
    fma2(c1, A[5], k[5]);
    fma2(c2, A[6], k[6]);
    fma2(c3, A[7], k[7]);
    unsigned long long d0 = add2(c0, c1);
    unsigned long long d1 = add2(c2, c3);
    unsigned long long e = add2(d0, d1);
    return lo32(e) + hi32(e);
}
__device__ __forceinline__ float sigm(float x) { return 1.0f / (1.0f + expf(-x)); }

// ---------------- fp16 helpers ----------------
__device__ __forceinline__ unsigned int h2u(__half2 h) {
    return *(unsigned int*)&h;
}

// ---------------- mma m16n8k16 fp16 ----------------
__device__ __forceinline__ void mma_f16(float* c, const unsigned int* a,
                                        unsigned int b0, unsigned int b1) {
    asm volatile(
        "mma.sync.aligned.m16n8k16.row.col.f32.f16.f16.f32 "
        "{%0,%1,%2,%3}, {%4,%5,%6,%7}, {%8,%9}, {%0,%1,%2,%3};"
        : "+f"(c[0]), "+f"(c[1]), "+f"(c[2]), "+f"(c[3])
        : "r"(a[0]), "r"(a[1]), "r"(a[2]), "r"(a[3]), "r"(b0), "r"(b1));
}

// ---------------- ldmatrix ----------------
#define LDSM_X4(r0, r1, r2, r3, addr) \
    asm volatile("ldmatrix.sync.aligned.m8n8.x4.shared.b16 {%0,%1,%2,%3}, [%4];" \
                 : "=r"(r0), "=r"(r1), "=r"(r2), "=r"(r3) : "r"(addr))
#define LDSM_X2(r0, r1, addr) \
    asm volatile("ldmatrix.sync.aligned.m8n8.x2.shared.b16 {%0,%1}, [%2];" \
                 : "=r"(r0), "=r"(r1) : "r"(addr))

// ---------------- cp.async helpers ----------------
__device__ __forceinline__ void cp_async16(unsigned int saddr, const void* g) {
    asm volatile("cp.async.cg.shared.global [%0], [%1], 16;"
                 :: "r"(saddr), "l"(__cvta_generic_to_global(g)) : "memory");
}
#define CP_COMMIT() asm volatile("cp.async.commit_group;" ::: "memory")
#define CP_WAIT(n)  asm volatile("cp.async.wait_group %0;" :: "n"(n) : "memory")

// ---------------- kernel 0a: pack scaled weights to fp16 ----------------
__global__ void pack_wbf(const float* __restrict__ Wq, const float* __restrict__ Wk,
                         const float* __restrict__ Wv, const float* __restrict__ Wbw,
                         const float* __restrict__ Waw) {
    int idx = blockIdx.x * blockDim.x + threadIdx.x;
    if (idx >= 256 * 128) return;
    int n = idx >> 7;
    int c = idx & 127;
    int k0 = 2 * c;
    float x = 0.0f, y = 0.0f;
    if (n < 64)        { x = Wq[n * JD + k0];        y = Wq[n * JD + k0 + 1]; }
    else if (n < 128)  { x = Wk[(n-64) * JD + k0];   y = Wk[(n-64) * JD + k0 + 1]; }
    else if (n < 192)  { x = Wv[(n-128) * JD + k0];  y = Wv[(n-128) * JD + k0 + 1]; }
    else if (n < 196)  { x = Wbw[(n-192) * JD + k0]; y = Wbw[(n-192) * JD + k0 + 1]; }
    else if (n < 200)  { x = Waw[(n-196) * JD + k0]; y = Waw[(n-196) * JD + k0 + 1]; }
    __half hx = __float2half_rn(x * WSCALE);
    __half hy = __float2half_rn(y * WSCALE);
    g_wh[idx] = ((unsigned int)__half_as_ushort(hy) << 16) | __half_as_ushort(hx);
}

// ---------------- kernel 0b: transpose out_w ----------------
__global__ void pack_outw(const float* __restrict__ out_w) {
    int idx = blockIdx.x * blockDim.x + threadIdx.x;
    if (idx >= KOUT * MEMD) return;
    int k = idx / MEMD;
    int m = idx % MEMD;
    g_wtr[m * KOUT + k] = out_w[idx];
}

// ---------------- kernel 1: single-barrier pipelined fp16 GEMM + fused epilogue ---
// BM=64, BN=128 (grid.y), BK=32 x 8 chunks, 128 threads = 4 warps.
// Triple-buffered A (STS from reg prefetch) and B (cp.async): ONE __syncthreads
// per kc. 5 blocks/SM (20 warps) — smem 46080*5 = 230400 <= 228KB carveout.
__global__ __launch_bounds__(128, 5) void gemm_tc2(
        const float* __restrict__ X,
        const float* __restrict__ curv, const float* __restrict__ ent,
        const float* __restrict__ Wbb,  const float* __restrict__ Wab,
        const float* __restrict__ curv_w, const float* __restrict__ ent_w,
        const float* __restrict__ lnqw, const float* __restrict__ lnqb,
        const float* __restrict__ lnkw, const float* __restrict__ lnkb) {
    extern __shared__ __align__(16) char dsm[];
    unsigned int* As = (unsigned int*)dsm;            // [3][64][ABS] fp16 pairs
    unsigned int* Bs = As + 3 * A_BUF_W;              // [3][128][ABS]
    float* Cs = (float*)dsm;                          // [64][132] (aliases; < GEMM_SMEM)

    int tid = threadIdx.x;
    int lane = tid & 31;
    int warp = tid >> 5;
    int g = lane >> 2;
    int tg = lane & 3;
    int m0 = blockIdx.x * 64;
    int n0 = blockIdx.y * 128;

    unsigned int sb_as = (unsigned int)__cvta_generic_to_shared(As);
    unsigned int sb_bs = (unsigned int)__cvta_generic_to_shared(Bs);

    // ldmatrix lane-role offsets (word units)
    int grp = lane >> 3;
    int wi = lane & 7;
    int laneA = ((grp & 1) * 8 + wi) * ABS + (grp >> 1) * 4;
    int laneB2 = ((grp >> 1) * 8 + wi) * ABS + (grp & 1) * 4;
    int laneG = wi * ABS + ((lane >> 3) & 1) * 4;

    int am = tid >> 3;           // A staging base row; r adds 16 rows
    int aq = tid & 7;
    int bsn = tid >> 2;          // B staging n base
    int bscq = tid & 3;

    float4 pa[4];
#pragma unroll
    for (int r = 0; r < 4; r++)
        pa[r] = *(const float4*)(X + (size_t)(m0 + am + 16 * r) * JD + aq * 4);
    // stage A(0) -> buf0
#pragma unroll
    for (int r = 0; r < 4; r++) {
        int m = am + 16 * r;
        unsigned int w0 = h2u(__floats2half2_rn(pa[r].x, pa[r].y));
        unsigned int w1 = h2u(__floats2half2_rn(pa[r].z, pa[r].w));
        *(uint2*)(&As[m * ABS + 2 * aq]) = make_uint2(w0, w1);
    }
    // cp.async B(0) -> buf0
#pragma unroll
    for (int r = 0; r < 4; r++)
        cp_async16(sb_bs + ((bsn + 32 * r) * ABS + bscq * 4) * 4,
                   g_wh + (n0 + bsn + 32 * r) * 128 + bscq * 4);
    CP_COMMIT();
    // prefetch A(1)
#pragma unroll
    for (int r = 0; r < 4; r++)
        pa[r] = *(const float4*)(X + (size_t)(m0 + am + 16 * r) * JD + 32 + aq * 4);

    if (blockIdx.y == 0) {
        // ---- full-width path (q/k): warp tile 32x64 ----
        int wm = warp & 1;
        int wn = warp >> 1;
        float acc[2][8][4];
#pragma unroll
        for (int mt = 0; mt < 2; mt++)
#pragma unroll
            for (int nt = 0; nt < 8; nt++)
#pragma unroll
                for (int i = 0; i < 4; i++) acc[mt][nt][i] = 0.0f;

        for (int kc = 0; kc < 8; kc++) {
            int nb = (kc + 1) % 3;
            if (kc < 7) {
                // stage A(kc+1) -> buf nb
#pragma unroll
                for (int r = 0; r < 4; r++) {
                    int m = am + 16 * r;
                    unsigned int w0 = h2u(__floats2half2_rn(pa[r].x, pa[r].y));
                    unsigned int w1 = h2u(__floats2half2_rn(pa[r].z, pa[r].w));
                    *(uint2*)(&As[nb * A_BUF_W + m * ABS + 2 * aq]) = make_uint2(w0, w1);
                }
                if (kc < 6) {
#pragma unroll
                    for (int r = 0; r < 4; r++)
                        pa[r] = *(const float4*)(X + (size_t)(m0 + am + 16 * r) * JD +
                                                 (kc + 2) * 32 + aq * 4);
                }
                unsigned int bbase = sb_bs + nb * B_BUF_W * 4;
#pragma unroll
                for (int r = 0; r < 4; r++)
                    cp_async16(bbase + ((bsn + 32 * r) * ABS + bscq * 4) * 4,
                               g_wh + (n0 + bsn + 32 * r) * 128 + (kc + 1) * 16 + bscq * 4);
                CP_COMMIT();
                CP_WAIT(1);
            } else {
                CP_WAIT(0);
            }
            __syncthreads();

            int cb = kc % 3;
            unsigned int bufA = sb_as + cb * A_BUF_W * 4;
            unsigned int bufB = sb_bs + cb * B_BUF_W * 4;
#pragma unroll
            for (int kt = 0; kt < 2; kt++) {
                unsigned int ah[2][4];
#pragma unroll
                for (int mt = 0; mt < 2; mt++) {
                    int mrow = wm * 32 + mt * 16;
                    unsigned int aaddr = bufA + (mrow * ABS + kt * 8 + laneA) * 4;
                    LDSM_X4(ah[mt][0], ah[mt][1], ah[mt][2], ah[mt][3], aaddr);
                }
                unsigned int bbase2 = bufB + ((wn * 64) * ABS + kt * 8 + laneB2) * 4;
#pragma unroll
                for (int ntp = 0; ntp < 4; ntp++) {
                    unsigned int b0, b1, b2, b3;
                    LDSM_X4(b0, b1, b2, b3, bbase2 + ntp * 16 * ABS * 4);
#pragma unroll
                    for (int mt = 0; mt < 2; mt++) {
                        mma_f16(acc[mt][2 * ntp],     ah[mt], b0, b1);
                        mma_f16(acc[mt][2 * ntp + 1], ah[mt], b2, b3);
                    }
                }
            }
        }
        __syncthreads();

#pragma unroll
        for (int mt = 0; mt < 2; mt++) {
#pragma unroll
            for (int nt = 0; nt < 8; nt++) {
                int row = wm * 32 + mt * 16 + g;
                int col = wn * 64 + nt * 8 + 2 * tg;
                Cs[row * 132 + col]           = acc[mt][nt][0];
                Cs[row * 132 + col + 1]       = acc[mt][nt][1];
                Cs[(row + 8) * 132 + col]     = acc[mt][nt][2];
                Cs[(row + 8) * 132 + col + 1] = acc[mt][nt][3];
            }
        }
    } else {
        // ---- reduced path (v + gates): warp = one 16-row m-tile, 9 n-tiles ----
        float accv[8][4];
        float accg[4];
#pragma unroll
        for (int nt = 0; nt < 8; nt++)
#pragma unroll
            for (int i = 0; i < 4; i++) accv[nt][i] = 0.0f;
#pragma unroll
        for (int i = 0; i < 4; i++) accg[i] = 0.0f;

        for (int kc = 0; kc < 8; kc++) {
            int nb = (kc + 1) % 3;
            if (kc < 7) {
#pragma unroll
                for (int r = 0; r < 4; r++) {
                    int m = am + 16 * r;
                    unsigned int w0 = h2u(__floats2half2_rn(pa[r].x, pa[r].y));
                    unsigned int w1 = h2u(__floats2half2_rn(pa[r].z, pa[r].w));
                    *(uint2*)(&As[nb * A_BUF_W + m * ABS + 2 * aq]) = make_uint2(w0, w1);
                }
                if (kc < 6) {
#pragma unroll
                    for (int r = 0; r < 4; r++)
                        pa[r] = *(const float4*)(X + (size_t)(m0 + am + 16 * r) * JD +
                                                 (kc + 2) * 32 + aq * 4);
                }
                unsigned int bbase = sb_bs + nb * B_BUF_W * 4;
#pragma unroll
                for (int r = 0; r < 4; r++)
                    cp_async16(bbase + ((bsn + 32 * r) * ABS + bscq * 4) * 4,
                               g_wh + (n0 + bsn + 32 * r) * 128 + (kc + 1) * 16 + bscq * 4);
                CP_COMMIT();
                CP_WAIT(1);
            } else {
                CP_WAIT(0);
            }
            __syncthreads();

            int cb = kc % 3;
            unsigned int bufA = sb_as + cb * A_BUF_W * 4;
            unsigned int bufB = sb_bs + cb * B_BUF_W * 4;
#pragma unroll
            for (int kt = 0; kt < 2; kt++) {
                unsigned int ah[4];
                {
                    int mrow = warp * 16;
                    unsigned int aaddr = bufA + (mrow * ABS + kt * 8 + laneA) * 4;
                    LDSM_X4(ah[0], ah[1], ah[2], ah[3], aaddr);
                }
                unsigned int bbase2 = bufB + (kt * 8 + laneB2) * 4;
#pragma unroll
                for (int ntp = 0; ntp < 4; ntp++) {
                    unsigned int b0, b1, b2, b3;
                    LDSM_X4(b0, b1, b2, b3, bbase2 + ntp * 16 * ABS * 4);
                    mma_f16(accv[2 * ntp],     ah, b0, b1);
                    mma_f16(accv[2 * ntp + 1], ah, b2, b3);
                }
                {
                    unsigned int b0, b1;
                    LDSM_X2(b0, b1, bufB + (64 * ABS + kt * 8 + laneG) * 4);
                    mma_f16(accg, ah, b0, b1);
                }
            }
        }
        __syncthreads();

        {
            int row = warp * 16 + g;
#pragma unroll
            for (int nt = 0; nt < 8; nt++) {
                int col = nt * 8 + 2 * tg;
                Cs[row * 132 + col]           = accv[nt][0];
                Cs[row * 132 + col + 1]       = accv[nt][1];
                Cs[(row + 8) * 132 + col]     = accv[nt][2];
                Cs[(row + 8) * 132 + col + 1] = accv[nt][3];
            }
            int col = 64 + 2 * tg;
            Cs[row * 132 + col]           = accg[0];
            Cs[row * 132 + col + 1]       = accg[1];
            Cs[(row + 8) * 132 + col]     = accg[2];
            Cs[(row + 8) * 132 + col + 1] = accg[3];
        }
    }
    __syncthreads();

    // ---------------- fused epilogue (with 2^-14 descale) ----------------
    int tx = tid & 7;
    int ty = tid >> 3;

#pragma unroll
    for (int rr = 0; rr < 4; rr++) {
        int row = ty * 4 + rr;
        int mtok = m0 + row;
        int n = mtok >> 11, t = mtok & 2047;
        const float* crow = Cs + row * 132 + tx * 16;

        if (blockIdx.y == 0) {
            float y[16];
            *(float4*)&y[0]  = *(const float4*)(crow + 0);
            *(float4*)&y[4]  = *(const float4*)(crow + 4);
            *(float4*)&y[8]  = *(const float4*)(crow + 8);
            *(float4*)&y[12] = *(const float4*)(crow + 12);
#pragma unroll
            for (int i = 0; i < 16; i++) y[i] *= DESC;
            float s = 0.0f;
#pragma unroll
            for (int i = 0; i < 16; i++) s += y[i];
            float mean = s * 0.0625f;
            float var = 0.0f;
#pragma unroll
            for (int i = 0; i < 16; i++) { float d = y[i] - mean; var = fmaf(d, d, var); }
            var *= 0.0625f;
            float inv = rsqrtf(var + EPS_LN);
            if (tx < 4) {
#pragma unroll
                for (int i = 0; i < 16; i++)
                    y[i] = fmaf((y[i] - mean) * inv, __ldg(lnqw + i), __ldg(lnqb + i));
                size_t base = ((size_t)(n * NH + tx) * SEQ_T + t) * DH;
                *(float4*)(g_q + base + 0)  = *(float4*)&y[0];
                *(float4*)(g_q + base + 4)  = *(float4*)&y[4];
                *(float4*)(g_q + base + 8)  = *(float4*)&y[8];
                *(float4*)(g_q + base + 12) = *(float4*)&y[12];
            } else {
                int h = tx - 4;
#pragma unroll
                for (int i = 0; i < 16; i++)
                    y[i] = fmaf((y[i] - mean) * inv, __ldg(lnkw + i), __ldg(lnkb + i));
                float nrm = 0.0f;
#pragma unroll
                for (int i = 0; i < 16; i++) nrm = fmaf(y[i], y[i], nrm);
                float rinv = 1.0f / fmaxf(sqrtf(nrm), 1e-12f);
#pragma unroll
                for (int i = 0; i < 16; i++) y[i] *= rinv;
                size_t base = ((size_t)(n * NH + h) * SEQ_T + t) * DH;
                *(float4*)(g_k + base + 0)  = *(float4*)&y[0];
                *(float4*)(g_k + base + 4)  = *(float4*)&y[4];
                *(float4*)(g_k + base + 8)  = *(float4*)&y[8];
                *(float4*)(g_k + base + 12) = *(float4*)&y[12];
            }
        } else {
            if (tx < 4) {
                float y[16];
                *(float4*)&y[0]  = *(const float4*)(crow + 0);
                *(float4*)&y[4]  = *(const float4*)(crow + 4);
                *(float4*)&y[8]  = *(const float4*)(crow + 8);
                *(float4*)&y[12] = *(const float4*)(crow + 12);
#pragma unroll
                for (int i = 0; i < 16; i++) y[i] *= DESC;
                size_t base = ((size_t)(n * NH + tx) * SEQ_T + t) * DH;
                *(float4*)(g_v + base + 0)  = *(float4*)&y[0];
                *(float4*)(g_v + base + 4)  = *(float4*)&y[4];
                *(float4*)(g_v + base + 8)  = *(float4*)&y[8];
                *(float4*)(g_v + base + 12) = *(float4*)&y[12];
            } else if (tx == 4) {
                float y[8];
                *(float4*)&y[0] = *(const float4*)(crow + 0);
                *(float4*)&y[4] = *(const float4*)(crow + 4);
#pragma unroll
                for (int i = 0; i < 8; i++) y[i] *= DESC;
                int b = n >> 4;
                float Kv = fminf(fabsf(__ldg(curv + b)), 10.0f);
                float Sv = fminf(fmaxf(__ldg(ent + b), 0.0f), 5.0f);
#pragma unroll
                for (int h = 0; h < 4; h++) {
                    float be = sigm(y[h] + __ldg(Wbb + h));
                    be = sigm(fmaf(Kv, __ldg(curv_w + h), be));
                    float al = sigm(y[4 + h] + __ldg(Wab + h));
                    al = sigm(fmaf(Sv, __ldg(ent_w + h), al));
                    g_beta[(n * NH + h) * SEQ_T + t] = be;
                    g_alpha[(n * NH + h) * SEQ_T + t] = al;
                }
            }
        }
    }
}

// ---------------- kernel 2a: chunked scan phase1 ----------------
__global__ __launch_bounds__(128) void scan_phase1() {
    __shared__ float sk[8][512];
    __shared__ float sv[8][512];
    __shared__ float sb[8][32];
    __shared__ float sa[8][32];

    int warp = threadIdx.x >> 5;
    int lane = threadIdx.x & 31;
    int g = lane >> 4;
    int row = lane & 15;
    int wg = warp * 2 + g;
    int grp = blockIdx.x * 8 + wg;

    unsigned long long P[8], R[8];
#pragma unroll
    for (int j = 0; j < 8; j++) { P[j] = 0ull; R[j] = 0ull; }
    P[row >> 1] = (row & 1) ? pack2(0.0f, 1.0f) : pack2(1.0f, 0.0f);

    for (int sub = 0; sub < CH / 32; sub++) {
        __syncwarp();
#pragma unroll
        for (int r = 0; r < 8; r++) {
            int f = lane + 32 * r;
            int gg = f >> 7;
            int e = f & 127;
            int grp2 = blockIdx.x * 8 + warp * 2 + gg;
            int rec2 = grp2 >> 4, ch2 = grp2 & 15;
            size_t base4 = ((size_t)rec2 * SEQ_T + ch2 * CH + sub * 32) * 4;
            ((float4*)sk[warp * 2 + gg])[e] = ((const float4*)g_k)[base4 + e];
            ((float4*)sv[warp * 2 + gg])[e] = ((const float4*)g_v)[base4 + e];
        }
#pragma unroll
        for (int r = 0; r < 2; r++) {
            int f = lane + 32 * r;
            int gg = f >> 5;
            int e = f & 31;
            int grp2 = blockIdx.x * 8 + warp * 2 + gg;
            int rec2 = grp2 >> 4, ch2 = grp2 & 15;
            int src = rec2 * SEQ_T + ch2 * CH + sub * 32 + e;
            sb[warp * 2 + gg][e] = g_beta[src];
            sa[warp * 2 + gg][e] = g_alpha[src];
        }
        __syncwarp();

        for (int s = 0; s < 32; s++) {
            unsigned long long kp[8];
            const unsigned long long* kptr = (const unsigned long long*)&sk[wg][s * 16];
#pragma unroll
            for (int j = 0; j < 8; j++) kp[j] = kptr[j];
            float vi = sv[wg][s * 16 + row];
            float be = sb[wg][s];
            float al = sa[wg][s];

            float u = dot16(P, kp);
            float w = dot16(R, kp);
            unsigned long long cu = dup2(-al * u);
            unsigned long long cr = dup2(fmaf(be, vi, -al * w));
#pragma unroll
            for (int j = 0; j < 8; j++) {
                fma2(P[j], cu, kp[j]);
                fma2(R[j], cr, kp[j]);
            }
        }
    }

    size_t obase = ((size_t)grp * 16 + row) * 16;
    unsigned long long* gp = (unsigned long long*)(g_P + obase);
    unsigned long long* gr = (unsigned long long*)(g_R + obase);
#pragma unroll
    for (int j = 0; j < 8; j++) { gp[j] = P[j]; gr[j] = R[j]; }
}

// ---------------- kernel 2b: serial combine ----------------
__global__ __launch_bounds__(128) void scan_combine() {
    __shared__ float sp[8][256];
    __shared__ float sr[8][256];

    int warp = threadIdx.x >> 5;
    int lane = threadIdx.x & 31;
    int g = lane >> 4;
    int row = lane & 15;
    int wg = warp * 2 + g;
    int rec = blockIdx.x * 8 + wg;

    unsigned long long S[8];
#pragma unroll
    for (int j = 0; j < 8; j++) S[j] = 0ull;

    for (int c = 0; c < NCH; c++) {
        size_t sbase = (((size_t)rec * NCH + c) * 16 + row) * 16;
        unsigned long long* gs = (unsigned long long*)(g_S + sbase);
#pragma unroll
        for (int j = 0; j < 8; j++) gs[j] = S[j];

        __syncwarp();
#pragma unroll
        for (int r = 0; r < 4; r++) {
            int f = lane + 32 * r;
            int gg = f >> 6;
            int e = f & 63;
            int rec2 = blockIdx.x * 8 + warp * 2 + gg;
            size_t base4 = ((size_t)rec2 * NCH + c) * 64;
            ((float4*)sp[warp * 2 + gg])[e] = ((const float4*)g_P)[base4 + e];
            ((float4*)sr[warp * 2 + gg])[e] = ((const float4*)g_R)[base4 + e];
        }
        __syncwarp();

        unsigned long long accm[8];
        const unsigned long long* rrow = (const unsigned long long*)&sr[wg][row * 16];
#pragma unroll
        for (int j = 0; j < 8; j++) accm[j] = rrow[j];
#pragma unroll
        for (int l = 0; l < 16; l++) {
            float sl = (l & 1) ? hi32(S[l >> 1]) : lo32(S[l >> 1]);
            unsigned long long sd = dup2(sl);
            const unsigned long long* prow = (const unsigned long long*)&sp[wg][l * 16];
#pragma unroll
            for (int j = 0; j < 8; j++) fma2(accm[j], sd, prow[j]);
        }
#pragma unroll
        for (int j = 0; j < 8; j++) S[j] = accm[j];
    }
}

// ---------------- kernel 2c: chunked scan phase3 ----------------
__global__ __launch_bounds__(128) void scan_phase3() {
    __shared__ float sk[8][512];
    __shared__ float sq[8][512];
    __shared__ float sv[8][512];
    __shared__ float sb[8][32];
    __shared__ float sa[8][32];

    int warp = threadIdx.x >> 5;
    int lane = threadIdx.x & 31;
    int g = lane >> 4;
    int row = lane & 15;
    int wg = warp * 2 + g;
    int grp = blockIdx.x * 8 + wg;

    unsigned long long M[8];
    {
        size_t sbase = ((size_t)grp * 16 + row) * 16;
        const unsigned long long* gs = (const unsigned long long*)(g_S + sbase);
#pragma unroll
        for (int j = 0; j < 8; j++) M[j] = gs[j];
    }

    for (int sub = 0; sub < CH / 32; sub++) {
        __syncwarp();
#pragma unroll
        for (int r = 0; r < 8; r++) {
            int f = lane + 32 * r;
            int gg = f >> 7;
            int e = f & 127;
            int grp2 = blockIdx.x * 8 + warp * 2 + gg;
            int rec2 = grp2 >> 4, ch2 = grp2 & 15;
            size_t base4 = ((size_t)rec2 * SEQ_T + ch2 * CH + sub * 32) * 4;
            ((float4*)sk[warp * 2 + gg])[e] = ((const float4*)g_k)[base4 + e];
            ((float4*)sq[warp * 2 + gg])[e] = ((const float4*)g_q)[base4 + e];
            ((float4*)sv[warp * 2 + gg])[e] = ((const float4*)g_v)[base4 + e];
        }
#pragma unroll
        for (int r = 0; r < 2; r++) {
            int f = lane + 32 * r;
            int gg = f >> 5;
            int e = f & 31;
            int grp2 = blockIdx.x * 8 + warp * 2 + gg;
            int rec2 = grp2 >> 4, ch2 = grp2 & 15;
            int src = rec2 * SEQ_T + ch2 * CH + sub * 32 + e;
            sb[warp * 2 + gg][e] = g_beta[src];
            sa[warp * 2 + gg][e] = g_alpha[src];
        }
        __syncwarp();

        for (int s = 0; s < 32; s++) {
            unsigned long long kp[8], qp[8];
            const unsigned long long* kptr = (const unsigned long long*)&sk[wg][s * 16];
            const unsigned long long* qptr = (const unsigned long long*)&sq[wg][s * 16];
#pragma unroll
            for (int j = 0; j < 8; j++) { kp[j] = kptr[j]; qp[j] = qptr[j]; }
            float vi = sv[wg][s * 16 + row];
            float be = sb[wg][s];
            float al = sa[wg][s];

            float mk = dot16(M, kp);
            unsigned long long cd = dup2(fmaf(be, vi, -al * mk));
#pragma unroll
            for (int j = 0; j < 8; j++) fma2(M[j], cd, kp[j]);
            float o = dot16(M, qp);
            sv[wg][s * 16 + row] = o;
        }
        __syncwarp();
#pragma unroll
        for (int r = 0; r < 8; r++) {
            int f = lane + 32 * r;
            int gg = f >> 7;
            int e = f & 127;
            int grp2 = blockIdx.x * 8 + warp * 2 + gg;
            int rec2 = grp2 >> 4, ch2 = grp2 & 15;
            size_t base4 = ((size_t)rec2 * SEQ_T + ch2 * CH + sub * 32) * 4;
            ((float4*)g_o)[base4 + e] = ((const float4*)sv[warp * 2 + gg])[e];
        }
    }
}

// ---------------- kernel 4: register-tiled output projection ----------------
__global__ __launch_bounds__(256) void final_proj(const float* __restrict__ out_b,
                                                  float* __restrict__ out) {
    extern __shared__ __align__(16) float fsm[];
    float* sw = fsm;                       // [64][192]
    float* so = fsm + 64 * 192;            // [64][FP_SOW]

    int tid = threadIdx.x;
    int tx = tid & 31;
    int ty = tid >> 5;
    int n = blockIdx.x;
    int t0 = blockIdx.y * FP_TT;
    int b = n >> 4;
    int p = n & 15;

    {
        int rr = tid >> 6;
        int cc = tid & 63;
#pragma unroll
        for (int m = 0; m < 16; m++) {
            int mr = m * 4 + rr;
#pragma unroll
            for (int j = 0; j < 3; j++)
                sw[mr * 192 + cc + 64 * j] = g_wtr[mr * 192 + cc + 64 * j];
        }
    }
#pragma unroll
    for (int r = 0; r < 16; r++) {
        int e = tid + 256 * r;
        int i = e & 15;
        int tt = (e >> 4) & 63;
        int h = e >> 10;
        so[(h * 16 + i) * FP_SOW + tt] =
            g_o[((size_t)(n * NH + h) * SEQ_T + t0 + tt) * DH + i];
    }
    __syncthreads();

    unsigned long long acc[8][3];
#pragma unroll
    for (int t = 0; t < 8; t++)
#pragma unroll
        for (int kp = 0; kp < 3; kp++) acc[t][kp] = 0ull;

#pragma unroll 4
    for (int m = 0; m < 64; m++) {
        const unsigned long long* wp = (const unsigned long long*)(sw + m * 192 + tx * 6);
        unsigned long long w0 = wp[0], w1 = wp[1], w2 = wp[2];
        const float* sop = so + m * FP_SOW + ty * 8;
#pragma unroll
        for (int t = 0; t < 8; t++) {
            unsigned long long sd = dup2(sop[t]);
            fma2(acc[t][0], sd, w0);
            fma2(acc[t][1], sd, w1);
            fma2(acc[t][2], sd, w2);
        }
    }

    float2 bias[3];
#pragma unroll
    for (int j = 0; j < 3; j++)
        bias[j] = *(const float2*)(out_b + tx * 6 + 2 * j);
#pragma unroll
    for (int t = 0; t < 8; t++) {
        int tt = t0 + ty * 8 + t;
        float* op = out + (((size_t)b * SEQ_T + tt) * N_P + p) * KOUT + tx * 6;
#pragma unroll
        for (int j = 0; j < 3; j++) {
            float2 v = make_float2(lo32(acc[t][j]) + bias[j].x,
                                   hi32(acc[t][j]) + bias[j].y);
            *(float2*)(op + 2 * j) = v;
        }
    }
}

// ---------------- launch ----------------
extern "C" void kernel_launch(void* const* d_in, const int* in_sizes, int n_in,
                              void* d_out, int out_size) {
    const float* joint  = (const float*)d_in[0];
    const float* curvat = (const float*)d_in[1];
    const float* entrop = (const float*)d_in[2];
    const float* Wq     = (const float*)d_in[3];
    const float* Wk     = (const float*)d_in[4];
    const float* Wv     = (const float*)d_in[5];
    const float* Wbw    = (const float*)d_in[6];
    const float* Wbb    = (const float*)d_in[7];
    const float* Waw    = (const float*)d_in[8];
    const float* Wab    = (const float*)d_in[9];
    const float* curv_w = (const float*)d_in[10];
    const float* ent_w  = (const float*)d_in[11];
    const float* out_w  = (const float*)d_in[12];
    const float* out_b  = (const float*)d_in[13];
    const float* lnqw   = (const float*)d_in[14];
    const float* lnqb   = (const float*)d_in[15];
    const float* lnkw   = (const float*)d_in[16];
    const float* lnkb   = (const float*)d_in[17];
    float* out = (float*)d_out;

    cudaFuncSetAttribute(gemm_tc2, cudaFuncAttributeMaxDynamicSharedMemorySize,
                         GEMM_SMEM);
    cudaFuncSetAttribute(final_proj, cudaFuncAttributeMaxDynamicSharedMemorySize,
                         FP_SMEM);

    pack_wbf<<<(256 * 128 + 255) / 256, 256>>>(Wq, Wk, Wv, Wbw, Waw);
    pack_outw<<<(KOUT * MEMD + 255) / 256, 256>>>(out_w);
    gemm_tc2<<<dim3(NT / 64, 2), 128, GEMM_SMEM>>>(joint, curvat, entrop, Wbb, Wab,
                                                   curv_w, ent_w, lnqw, lnqb,
                                                   lnkw, lnkb);
    scan_phase1<<<NGRP / 8, 128>>>();
    scan_combine<<<NREC / 8, 128>>>();
    scan_phase3<<<NGRP / 8, 128>>>();
    final_proj<<<dim3(NSEQ, SEQ_T / FP_TT), 256, FP_SMEM>>>(out_b, out);
}

// round 17
// speedup vs baseline: 1.2245x; 1.2245x over previous
#include <cuda_runtime.h>
#include <cuda_fp16.h>
#include <math.h>

// Problem constants
constexpr int N_B   = 4;
constexpr int SEQ_T = 2048;
constexpr int N_P   = 16;
constexpr int JD    = 256;
constexpr int NH    = 4;
constexpr int DH    = 16;
constexpr int MEMD  = 64;
constexpr int KOUT  = 192;
constexpr int NSEQ  = N_B * N_P;        // 64
constexpr int NT    = NSEQ * SEQ_T;     // 131072 tokens
constexpr float EPS_LN = 1e-5f;

// chunked-scan constants
constexpr int CH   = 128;
constexpr int NCH  = SEQ_T / CH;        // 16
constexpr int NREC = NSEQ * NH;         // 256
constexpr int NGRP = NREC * NCH;        // 4096

// GEMM constants
constexpr int ABS = 20;                     // padded word stride for smem rows
constexpr int A_BUF_W = 64 * ABS;           // words per A buffer = 1280
constexpr int B_BUF_W = 128 * ABS;          // words per B buffer = 2560
// staging: 3*A + 3*B = 11520 words = 46080 B; aliased C tile = 33792 B. staging dominates.
constexpr int GEMM_SMEM = 3 * (A_BUF_W + B_BUF_W) * 4;   // 46080
constexpr float WSCALE = 16384.0f;          // 2^14 pre-scale (fp16 subnormal guard)
constexpr float DESC   = 1.0f / 16384.0f;

// final_proj constants
constexpr int FP_TT   = 64;
constexpr int FP_SOW  = 66;
constexpr int FP_SMEM = (64 * 192 + 64 * FP_SOW) * 4;   // 66048 B

// ---------------- scratch (device globals; allocation-free) ----------------
__device__ unsigned int g_wh[256 * 128];     // W fp16 pairs (scaled), [n][c]
__device__ float g_wtr[MEMD * KOUT];
__device__ float g_q[(size_t)NREC * SEQ_T * DH];
__device__ float g_k[(size_t)NREC * SEQ_T * DH];
__device__ float g_v[(size_t)NREC * SEQ_T * DH];
__device__ float g_o[(size_t)NREC * SEQ_T * DH];
__device__ float g_beta[NREC * SEQ_T];
__device__ float g_alpha[NREC * SEQ_T];
__device__ float g_P[(size_t)NGRP * 256];
__device__ float g_R[(size_t)NGRP * 256];
__device__ float g_S[(size_t)NGRP * 256];

// ---------------- f32x2 helpers ----------------
__device__ __forceinline__ unsigned long long dup2(float x) {
    unsigned long long r;
    unsigned int xi = __float_as_uint(x);
    asm("mov.b64 %0, {%1, %1};" : "=l"(r) : "r"(xi));
    return r;
}
__device__ __forceinline__ unsigned long long pack2(float lo, float hi) {
    unsigned long long r;
    asm("mov.b64 %0, {%1, %2};" : "=l"(r) : "f"(lo), "f"(hi));
    return r;
}
__device__ __forceinline__ void fma2(unsigned long long& acc, unsigned long long a,
                                     unsigned long long b) {
    asm("fma.rn.f32x2 %0, %1, %2, %0;" : "+l"(acc) : "l"(a), "l"(b));
}
__device__ __forceinline__ unsigned long long mul2(unsigned long long a, unsigned long long b) {
    unsigned long long r;
    asm("mul.rn.f32x2 %0, %1, %2;" : "=l"(r) : "l"(a), "l"(b));
    return r;
}
__device__ __forceinline__ unsigned long long add2(unsigned long long a, unsigned long long b) {
    unsigned long long r;
    asm("add.rn.f32x2 %0, %1, %2;" : "=l"(r) : "l"(a), "l"(b));
    return r;
}
__device__ __forceinline__ float lo32(unsigned long long v) {
    return __uint_as_float((unsigned int)(v & 0xffffffffull));
}
__device__ __forceinline__ float hi32(unsigned long long v) {
    return __uint_as_float((unsigned int)(v >> 32));
}
__device__ __forceinline__ float dot16(const unsigned long long* A, const unsigned long long* k) {
    unsigned long long c0 = mul2(A[0], k[0]);
    unsigned long long c1 = mul2(A[1], k[1]);
    unsigned long long c2 = mul2(A[2], k[2]);
    unsigned long long c3 = mul2(A[3], k[3]);
    fma2(c0, A[4], k[4]);
    fma2(c1, A[5], k[5]);
    fma2(c2, A[6], k[6]);
    fma2(c3, A[7], k[7]);
    unsigned long long d0 = add2(c0, c1);
    unsigned long long d1 = add2(c2, c3);
    unsigned long long e = add2(d0, d1);
    return lo32(e) + hi32(e);
}
__device__ __forceinline__ float sigm(float x) { return 1.0f / (1.0f + expf(-x)); }

// ---------------- fp16 helpers ----------------
__device__ __forceinline__ unsigned int h2u(__half2 h) {
    return *(unsigned int*)&h;
}

// ---------------- mma m16n8k16 fp16 ----------------
__device__ __forceinline__ void mma_f16(float* c, const unsigned int* a,
                                        unsigned int b0, unsigned int b1) {
    asm volatile(
        "mma.sync.aligned.m16n8k16.row.col.f32.f16.f16.f32 "
        "{%0,%1,%2,%3}, {%4,%5,%6,%7}, {%8,%9}, {%0,%1,%2,%3};"
        : "+f"(c[0]), "+f"(c[1]), "+f"(c[2]), "+f"(c[3])
        : "r"(a[0]), "r"(a[1]), "r"(a[2]), "r"(a[3]), "r"(b0), "r"(b1));
}

// ---------------- ldmatrix ----------------
#define LDSM_X4(r0, r1, r2, r3, addr) \
    asm volatile("ldmatrix.sync.aligned.m8n8.x4.shared.b16 {%0,%1,%2,%3}, [%4];" \
                 : "=r"(r0), "=r"(r1), "=r"(r2), "=r"(r3) : "r"(addr))
#define LDSM_X2(r0, r1, addr) \
    asm volatile("ldmatrix.sync.aligned.m8n8.x2.shared.b16 {%0,%1}, [%2];" \
                 : "=r"(r0), "=r"(r1) : "r"(addr))

// ---------------- cp.async helpers ----------------
__device__ __forceinline__ void cp_async16(unsigned int saddr, const void* g) {
    asm volatile("cp.async.cg.shared.global [%0], [%1], 16;"
                 :: "r"(saddr), "l"(__cvta_generic_to_global(g)) : "memory");
}
#define CP_COMMIT() asm volatile("cp.async.commit_group;" ::: "memory")
#define CP_WAIT(n)  asm volatile("cp.async.wait_group %0;" :: "n"(n) : "memory")

// ---------------- kernel 0: pack weights (proj fp16 + out_w transpose) ----------
__global__ void pack_all(const float* __restrict__ Wq, const float* __restrict__ Wk,
                         const float* __restrict__ Wv, const float* __restrict__ Wbw,
                         const float* __restrict__ Waw,
                         const float* __restrict__ out_w) {
    int idx = blockIdx.x * blockDim.x + threadIdx.x;
    if (idx < 256 * 128) {
        int n = idx >> 7;
        int c = idx & 127;
        int k0 = 2 * c;
        float x = 0.0f, y = 0.0f;
        if (n < 64)        { x = Wq[n * JD + k0];        y = Wq[n * JD + k0 + 1]; }
        else if (n < 128)  { x = Wk[(n-64) * JD + k0];   y = Wk[(n-64) * JD + k0 + 1]; }
        else if (n < 192)  { x = Wv[(n-128) * JD + k0];  y = Wv[(n-128) * JD + k0 + 1]; }
        else if (n < 196)  { x = Wbw[(n-192) * JD + k0]; y = Wbw[(n-192) * JD + k0 + 1]; }
        else if (n < 200)  { x = Waw[(n-196) * JD + k0]; y = Waw[(n-196) * JD + k0 + 1]; }
        __half hx = __float2half_rn(x * WSCALE);
        __half hy = __float2half_rn(y * WSCALE);
        g_wh[idx] = ((unsigned int)__half_as_ushort(hy) << 16) | __half_as_ushort(hx);
    } else {
        int j = idx - 256 * 128;
        if (j < KOUT * MEMD) {
            int k = j / MEMD;
            int m = j % MEMD;
            g_wtr[m * KOUT + k] = out_w[j];
        }
    }
}

// ---------------- kernel 1: single-barrier pipelined fp16 GEMM + fused epilogue ---
// BM=64, BN=128 (grid.y), BK=32 x 8 chunks, 128 threads = 4 warps.
// Triple-buffered A (STS from reg prefetch) and B (cp.async): ONE __syncthreads
// per kc. 4 blocks/SM (RF hard cap at 128 regs/thread).
__global__ __launch_bounds__(128, 4) void gemm_tc2(
        const float* __restrict__ X,
        const float* __restrict__ curv, const float* __restrict__ ent,
        const float* __restrict__ Wbb,  const float* __restrict__ Wab,
        const float* __restrict__ curv_w, const float* __restrict__ ent_w,
        const float* __restrict__ lnqw, const float* __restrict__ lnqb,
        const float* __restrict__ lnkw, const float* __restrict__ lnkb) {
    extern __shared__ __align__(16) char dsm[];
    unsigned int* As = (unsigned int*)dsm;            // [3][64][ABS] fp16 pairs
    unsigned int* Bs = As + 3 * A_BUF_W;              // [3][128][ABS]
    float* Cs = (float*)dsm;                          // [64][132] (aliases; < GEMM_SMEM)

    int tid = threadIdx.x;
    int lane = tid & 31;
    int warp = tid >> 5;
    int g = lane >> 2;
    int tg = lane & 3;
    int m0 = blockIdx.x * 64;
    int n0 = blockIdx.y * 128;

    unsigned int sb_as = (unsigned int)__cvta_generic_to_shared(As);
    unsigned int sb_bs = (unsigned int)__cvta_generic_to_shared(Bs);

    // ldmatrix lane-role offsets (word units)
    int grp = lane >> 3;
    int wi = lane & 7;
    int laneA = ((grp & 1) * 8 + wi) * ABS + (grp >> 1) * 4;
    int laneB2 = ((grp >> 1) * 8 + wi) * ABS + (grp & 1) * 4;
    int laneG = wi * ABS + ((lane >> 3) & 1) * 4;

    int am = tid >> 3;           // A staging base row; r adds 16 rows
    int aq = tid & 7;
    int bsn = tid >> 2;          // B staging n base
    int bscq = tid & 3;

    float4 pa[4];
#pragma unroll
    for (int r = 0; r < 4; r++)
        pa[r] = *(const float4*)(X + (size_t)(m0 + am + 16 * r) * JD + aq * 4);
    // stage A(0) -> buf0
#pragma unroll
    for (int r = 0; r < 4; r++) {
        int m = am + 16 * r;
        unsigned int w0 = h2u(__floats2half2_rn(pa[r].x, pa[r].y));
        unsigned int w1 = h2u(__floats2half2_rn(pa[r].z, pa[r].w));
        *(uint2*)(&As[m * ABS + 2 * aq]) = make_uint2(w0, w1);
    }
    // cp.async B(0) -> buf0
#pragma unroll
    for (int r = 0; r < 4; r++)
        cp_async16(sb_bs + ((bsn + 32 * r) * ABS + bscq * 4) * 4,
                   g_wh + (n0 + bsn + 32 * r) * 128 + bscq * 4);
    CP_COMMIT();
    // prefetch A(1)
#pragma unroll
    for (int r = 0; r < 4; r++)
        pa[r] = *(const float4*)(X + (size_t)(m0 + am + 16 * r) * JD + 32 + aq * 4);

    if (blockIdx.y == 0) {
        // ---- full-width path (q/k): warp tile 32x64 ----
        int wm = warp & 1;
        int wn = warp >> 1;
        float acc[2][8][4];
#pragma unroll
        for (int mt = 0; mt < 2; mt++)
#pragma unroll
            for (int nt = 0; nt < 8; nt++)
#pragma unroll
                for (int i = 0; i < 4; i++) acc[mt][nt][i] = 0.0f;

        for (int kc = 0; kc < 8; kc++) {
            int nb = (kc + 1) % 3;
            if (kc < 7) {
                // stage A(kc+1) -> buf nb
#pragma unroll
                for (int r = 0; r < 4; r++) {
                    int m = am + 16 * r;
                    unsigned int w0 = h2u(__floats2half2_rn(pa[r].x, pa[r].y));
                    unsigned int w1 = h2u(__floats2half2_rn(pa[r].z, pa[r].w));
                    *(uint2*)(&As[nb * A_BUF_W + m * ABS + 2 * aq]) = make_uint2(w0, w1);
                }
                if (kc < 6) {
#pragma unroll
                    for (int r = 0; r < 4; r++)
                        pa[r] = *(const float4*)(X + (size_t)(m0 + am + 16 * r) * JD +
                                                 (kc + 2) * 32 + aq * 4);
                }
                unsigned int bbase = sb_bs + nb * B_BUF_W * 4;
#pragma unroll
                for (int r = 0; r < 4; r++)
                    cp_async16(bbase + ((bsn + 32 * r) * ABS + bscq * 4) * 4,
                               g_wh + (n0 + bsn + 32 * r) * 128 + (kc + 1) * 16 + bscq * 4);
                CP_COMMIT();
                CP_WAIT(1);
            } else {
                CP_WAIT(0);
            }
            __syncthreads();

            int cb = kc % 3;
            unsigned int bufA = sb_as + cb * A_BUF_W * 4;
            unsigned int bufB = sb_bs + cb * B_BUF_W * 4;
#pragma unroll
            for (int kt = 0; kt < 2; kt++) {
                unsigned int ah[2][4];
#pragma unroll
                for (int mt = 0; mt < 2; mt++) {
                    int mrow = wm * 32 + mt * 16;
                    unsigned int aaddr = bufA + (mrow * ABS + kt * 8 + laneA) * 4;
                    LDSM_X4(ah[mt][0], ah[mt][1], ah[mt][2], ah[mt][3], aaddr);
                }
                unsigned int bbase2 = bufB + ((wn * 64) * ABS + kt * 8 + laneB2) * 4;
#pragma unroll
                for (int ntp = 0; ntp < 4; ntp++) {
                    unsigned int b0, b1, b2, b3;
                    LDSM_X4(b0, b1, b2, b3, bbase2 + ntp * 16 * ABS * 4);
#pragma unroll
                    for (int mt = 0; mt < 2; mt++) {
                        mma_f16(acc[mt][2 * ntp],     ah[mt], b0, b1);
                        mma_f16(acc[mt][2 * ntp + 1], ah[mt], b2, b3);
                    }
                }
            }
        }
        __syncthreads();

#pragma unroll
        for (int mt = 0; mt < 2; mt++) {
#pragma unroll
            for (int nt = 0; nt < 8; nt++) {
                int row = wm * 32 + mt * 16 + g;
                int col = wn * 64 + nt * 8 + 2 * tg;
                Cs[row * 132 + col]           = acc[mt][nt][0];
                Cs[row * 132 + col + 1]       = acc[mt][nt][1];
                Cs[(row + 8) * 132 + col]     = acc[mt][nt][2];
                Cs[(row + 8) * 132 + col + 1] = acc[mt][nt][3];
            }
        }
    } else {
        // ---- reduced path (v + gates): warp = one 16-row m-tile, 9 n-tiles ----
        float accv[8][4];
        float accg[4];
#pragma unroll
        for (int nt = 0; nt < 8; nt++)
#pragma unroll
            for (int i = 0; i < 4; i++) accv[nt][i] = 0.0f;
#pragma unroll
        for (int i = 0; i < 4; i++) accg[i] = 0.0f;

        for (int kc = 0; kc < 8; kc++) {
            int nb = (kc + 1) % 3;
            if (kc < 7) {
#pragma unroll
                for (int r = 0; r < 4; r++) {
                    int m = am + 16 * r;
                    unsigned int w0 = h2u(__floats2half2_rn(pa[r].x, pa[r].y));
                    unsigned int w1 = h2u(__floats2half2_rn(pa[r].z, pa[r].w));
                    *(uint2*)(&As[nb * A_BUF_W + m * ABS + 2 * aq]) = make_uint2(w0, w1);
                }
                if (kc < 6) {
#pragma unroll
                    for (int r = 0; r < 4; r++)
                        pa[r] = *(const float4*)(X + (size_t)(m0 + am + 16 * r) * JD +
                                                 (kc + 2) * 32 + aq * 4);
                }
                unsigned int bbase = sb_bs + nb * B_BUF_W * 4;
#pragma unroll
                for (int r = 0; r < 4; r++)
                    cp_async16(bbase + ((bsn + 32 * r) * ABS + bscq * 4) * 4,
                               g_wh + (n0 + bsn + 32 * r) * 128 + (kc + 1) * 16 + bscq * 4);
                CP_COMMIT();
                CP_WAIT(1);
            } else {
                CP_WAIT(0);
            }
            __syncthreads();

            int cb = kc % 3;
            unsigned int bufA = sb_as + cb * A_BUF_W * 4;
            unsigned int bufB = sb_bs + cb * B_BUF_W * 4;
#pragma unroll
            for (int kt = 0; kt < 2; kt++) {
                unsigned int ah[4];
                {
                    int mrow = warp * 16;
                    unsigned int aaddr = bufA + (mrow * ABS + kt * 8 + laneA) * 4;
                    LDSM_X4(ah[0], ah[1], ah[2], ah[3], aaddr);
                }
                unsigned int bbase2 = bufB + (kt * 8 + laneB2) * 4;
#pragma unroll
                for (int ntp = 0; ntp < 4; ntp++) {
                    unsigned int b0, b1, b2, b3;
                    LDSM_X4(b0, b1, b2, b3, bbase2 + ntp * 16 * ABS * 4);
                    mma_f16(accv[2 * ntp],     ah, b0, b1);
                    mma_f16(accv[2 * ntp + 1], ah, b2, b3);
                }
                {
                    unsigned int b0, b1;
                    LDSM_X2(b0, b1, bufB + (64 * ABS + kt * 8 + laneG) * 4);
                    mma_f16(accg, ah, b0, b1);
                }
            }
        }
        __syncthreads();

        {
            int row = warp * 16 + g;
#pragma unroll
            for (int nt = 0; nt < 8; nt++) {
                int col = nt * 8 + 2 * tg;
                Cs[row * 132 + col]           = accv[nt][0];
                Cs[row * 132 + col + 1]       = accv[nt][1];
                Cs[(row + 8) * 132 + col]     = accv[nt][2];
                Cs[(row + 8) * 132 + col + 1] = accv[nt][3];
            }
            int col = 64 + 2 * tg;
            Cs[row * 132 + col]           = accg[0];
            Cs[row * 132 + col + 1]       = accg[1];
            Cs[(row + 8) * 132 + col]     = accg[2];
            Cs[(row + 8) * 132 + col + 1] = accg[3];
        }
    }
    __syncthreads();

    // ---------------- fused epilogue (with 2^-14 descale) ----------------
    int tx = tid & 7;
    int ty = tid >> 3;

#pragma unroll
    for (int rr = 0; rr < 4; rr++) {
        int row = ty * 4 + rr;
        int mtok = m0 + row;
        int n = mtok >> 11, t = mtok & 2047;
        const float* crow = Cs + row * 132 + tx * 16;

        if (blockIdx.y == 0) {
            float y[16];
            *(float4*)&y[0]  = *(const float4*)(crow + 0);
            *(float4*)&y[4]  = *(const float4*)(crow + 4);
            *(float4*)&y[8]  = *(const float4*)(crow + 8);
            *(float4*)&y[12] = *(const float4*)(crow + 12);
#pragma unroll
            for (int i = 0; i < 16; i++) y[i] *= DESC;
            float s = 0.0f;
#pragma unroll
            for (int i = 0; i < 16; i++) s += y[i];
            float mean = s * 0.0625f;
            float var = 0.0f;
#pragma unroll
            for (int i = 0; i < 16; i++) { float d = y[i] - mean; var = fmaf(d, d, var); }
            var *= 0.0625f;
            float inv = rsqrtf(var + EPS_LN);
            if (tx < 4) {
#pragma unroll
                for (int i = 0; i < 16; i++)
                    y[i] = fmaf((y[i] - mean) * inv, __ldg(lnqw + i), __ldg(lnqb + i));
                size_t base = ((size_t)(n * NH + tx) * SEQ_T + t) * DH;
                *(float4*)(g_q + base + 0)  = *(float4*)&y[0];
                *(float4*)(g_q + base + 4)  = *(float4*)&y[4];
                *(float4*)(g_q + base + 8)  = *(float4*)&y[8];
                *(float4*)(g_q + base + 12) = *(float4*)&y[12];
            } else {
                int h = tx - 4;
#pragma unroll
                for (int i = 0; i < 16; i++)
                    y[i] = fmaf((y[i] - mean) * inv, __ldg(lnkw + i), __ldg(lnkb + i));
                float nrm = 0.0f;
#pragma unroll
                for (int i = 0; i < 16; i++) nrm = fmaf(y[i], y[i], nrm);
                float rinv = 1.0f / fmaxf(sqrtf(nrm), 1e-12f);
#pragma unroll
                for (int i = 0; i < 16; i++) y[i] *= rinv;
                size_t base = ((size_t)(n * NH + h) * SEQ_T + t) * DH;
                *(float4*)(g_k + base + 0)  = *(float4*)&y[0];
                *(float4*)(g_k + base + 4)  = *(float4*)&y[4];
                *(float4*)(g_k + base + 8)  = *(float4*)&y[8];
                *(float4*)(g_k + base + 12) = *(float4*)&y[12];
            }
        } else {
            if (tx < 4) {
                float y[16];
                *(float4*)&y[0]  = *(const float4*)(crow + 0);
                *(float4*)&y[4]  = *(const float4*)(crow + 4);
                *(float4*)&y[8]  = *(const float4*)(crow + 8);
                *(float4*)&y[12] = *(const float4*)(crow + 12);
#pragma unroll
                for (int i = 0; i < 16; i++) y[i] *= DESC;
                size_t base = ((size_t)(n * NH + tx) * SEQ_T + t) * DH;
                *(float4*)(g_v + base + 0)  = *(float4*)&y[0];
                *(float4*)(g_v + base + 4)  = *(float4*)&y[4];
                *(float4*)(g_v + base + 8)  = *(float4*)&y[8];
                *(float4*)(g_v + base + 12) = *(float4*)&y[12];
            } else if (tx == 4) {
                float y[8];
                *(float4*)&y[0] = *(const float4*)(crow + 0);
                *(float4*)&y[4] = *(const float4*)(crow + 4);
#pragma unroll
                for (int i = 0; i < 8; i++) y[i] *= DESC;
                int b = n >> 4;
                float Kv = fminf(fabsf(__ldg(curv + b)), 10.0f);
                float Sv = fminf(fmaxf(__ldg(ent + b), 0.0f), 5.0f);
#pragma unroll
                for (int h = 0; h < 4; h++) {
                    float be = sigm(y[h] + __ldg(Wbb + h));
                    be = sigm(fmaf(Kv, __ldg(curv_w + h), be));
                    float al = sigm(y[4 + h] + __ldg(Wab + h));
                    al = sigm(fmaf(Sv, __ldg(ent_w + h), al));
                    g_beta[(n * NH + h) * SEQ_T + t] = be;
                    g_alpha[(n * NH + h) * SEQ_T + t] = al;
                }
            }
        }
    }
}

// ---------------- kernel 2a: chunked scan phase1 ----------------
__global__ __launch_bounds__(128) void scan_phase1() {
    __shared__ float sk[8][512];
    __shared__ float sv[8][512];
    __shared__ float sb[8][32];
    __shared__ float sa[8][32];

    int warp = threadIdx.x >> 5;
    int lane = threadIdx.x & 31;
    int g = lane >> 4;
    int row = lane & 15;
    int wg = warp * 2 + g;
    int grp = blockIdx.x * 8 + wg;

    unsigned long long P[8], R[8];
#pragma unroll
    for (int j = 0; j < 8; j++) { P[j] = 0ull; R[j] = 0ull; }
    P[row >> 1] = (row & 1) ? pack2(0.0f, 1.0f) : pack2(1.0f, 0.0f);

    for (int sub = 0; sub < CH / 32; sub++) {
        __syncwarp();
#pragma unroll
        for (int r = 0; r < 8; r++) {
            int f = lane + 32 * r;
            int gg = f >> 7;
            int e = f & 127;
            int grp2 = blockIdx.x * 8 + warp * 2 + gg;
            int rec2 = grp2 >> 4, ch2 = grp2 & 15;
            size_t base4 = ((size_t)rec2 * SEQ_T + ch2 * CH + sub * 32) * 4;
            ((float4*)sk[warp * 2 + gg])[e] = ((const float4*)g_k)[base4 + e];
            ((float4*)sv[warp * 2 + gg])[e] = ((const float4*)g_v)[base4 + e];
        }
#pragma unroll
        for (int r = 0; r < 2; r++) {
            int f = lane + 32 * r;
            int gg = f >> 5;
            int e = f & 31;
            int grp2 = blockIdx.x * 8 + warp * 2 + gg;
            int rec2 = grp2 >> 4, ch2 = grp2 & 15;
            int src = rec2 * SEQ_T + ch2 * CH + sub * 32 + e;
            sb[warp * 2 + gg][e] = g_beta[src];
            sa[warp * 2 + gg][e] = g_alpha[src];
        }
        __syncwarp();

        for (int s = 0; s < 32; s++) {
            unsigned long long kp[8];
            const unsigned long long* kptr = (const unsigned long long*)&sk[wg][s * 16];
#pragma unroll
            for (int j = 0; j < 8; j++) kp[j] = kptr[j];
            float vi = sv[wg][s * 16 + row];
            float be = sb[wg][s];
            float al = sa[wg][s];

            float u = dot16(P, kp);
            float w = dot16(R, kp);
            unsigned long long cu = dup2(-al * u);
            unsigned long long cr = dup2(fmaf(be, vi, -al * w));
#pragma unroll
            for (int j = 0; j < 8; j++) {
                fma2(P[j], cu, kp[j]);
                fma2(R[j], cr, kp[j]);
            }
        }
    }

    size_t obase = ((size_t)grp * 16 + row) * 16;
    unsigned long long* gp = (unsigned long long*)(g_P + obase);
    unsigned long long* gr = (unsigned long long*)(g_R + obase);
#pragma unroll
    for (int j = 0; j < 8; j++) { gp[j] = P[j]; gr[j] = R[j]; }
}

// ---------------- kernel 2b: serial combine ----------------
__global__ __launch_bounds__(128) void scan_combine() {
    __shared__ float sp[8][256];
    __shared__ float sr[8][256];

    int warp = threadIdx.x >> 5;
    int lane = threadIdx.x & 31;
    int g = lane >> 4;
    int row = lane & 15;
    int wg = warp * 2 + g;
    int rec = blockIdx.x * 8 + wg;

    unsigned long long S[8];
#pragma unroll
    for (int j = 0; j < 8; j++) S[j] = 0ull;

    for (int c = 0; c < NCH; c++) {
        size_t sbase = (((size_t)rec * NCH + c) * 16 + row) * 16;
        unsigned long long* gs = (unsigned long long*)(g_S + sbase);
#pragma unroll
        for (int j = 0; j < 8; j++) gs[j] = S[j];

        __syncwarp();
#pragma unroll
        for (int r = 0; r < 4; r++) {
            int f = lane + 32 * r;
            int gg = f >> 6;
            int e = f & 63;
            int rec2 = blockIdx.x * 8 + warp * 2 + gg;
            size_t base4 = ((size_t)rec2 * NCH + c) * 64;
            ((float4*)sp[warp * 2 + gg])[e] = ((const float4*)g_P)[base4 + e];
            ((float4*)sr[warp * 2 + gg])[e] = ((const float4*)g_R)[base4 + e];
        }
        __syncwarp();

        unsigned long long accm[8];
        const unsigned long long* rrow = (const unsigned long long*)&sr[wg][row * 16];
#pragma unroll
        for (int j = 0; j < 8; j++) accm[j] = rrow[j];
#pragma unroll
        for (int l = 0; l < 16; l++) {
            float sl = (l & 1) ? hi32(S[l >> 1]) : lo32(S[l >> 1]);
            unsigned long long sd = dup2(sl);
            const unsigned long long* prow = (const unsigned long long*)&sp[wg][l * 16];
#pragma unroll
            for (int j = 0; j < 8; j++) fma2(accm[j], sd, prow[j]);
        }
#pragma unroll
        for (int j = 0; j < 8; j++) S[j] = accm[j];
    }
}

// ---------------- kernel 2c: chunked scan phase3 ----------------
__global__ __launch_bounds__(128) void scan_phase3() {
    __shared__ float sk[8][512];
    __shared__ float sq[8][512];
    __shared__ float sv[8][512];
    __shared__ float sb[8][32];
    __shared__ float sa[8][32];

    int warp = threadIdx.x >> 5;
    int lane = threadIdx.x & 31;
    int g = lane >> 4;
    int row = lane & 15;
    int wg = warp * 2 + g;
    int grp = blockIdx.x * 8 + wg;

    unsigned long long M[8];
    {
        size_t sbase = ((size_t)grp * 16 + row) * 16;
        const unsigned long long* gs = (const unsigned long long*)(g_S + sbase);
#pragma unroll
        for (int j = 0; j < 8; j++) M[j] = gs[j];
    }

    for (int sub = 0; sub < CH / 32; sub++) {
        __syncwarp();
#pragma unroll
        for (int r = 0; r < 8; r++) {
            int f = lane + 32 * r;
            int gg = f >> 7;
            int e = f & 127;
            int grp2 = blockIdx.x * 8 + warp * 2 + gg;
            int rec2 = grp2 >> 4, ch2 = grp2 & 15;
            size_t base4 = ((size_t)rec2 * SEQ_T + ch2 * CH + sub * 32) * 4;
            ((float4*)sk[warp * 2 + gg])[e] = ((const float4*)g_k)[base4 + e];
            ((float4*)sq[warp * 2 + gg])[e] = ((const float4*)g_q)[base4 + e];
            ((float4*)sv[warp * 2 + gg])[e] = ((const float4*)g_v)[base4 + e];
        }
#pragma unroll
        for (int r = 0; r < 2; r++) {
            int f = lane + 32 * r;
            int gg = f >> 5;
            int e = f & 31;
            int grp2 = blockIdx.x * 8 + warp * 2 + gg;
            int rec2 = grp2 >> 4, ch2 = grp2 & 15;
            int src = rec2 * SEQ_T + ch2 * CH + sub * 32 + e;
            sb[warp * 2 + gg][e] = g_beta[src];
            sa[warp * 2 + gg][e] = g_alpha[src];
        }
        __syncwarp();

        for (int s = 0; s < 32; s++) {
            unsigned long long kp[8], qp[8];
            const unsigned long long* kptr = (const unsigned long long*)&sk[wg][s * 16];
            const unsigned long long* qptr = (const unsigned long long*)&sq[wg][s * 16];
#pragma unroll
            for (int j = 0; j < 8; j++) { kp[j] = kptr[j]; qp[j] = qptr[j]; }
            float vi = sv[wg][s * 16 + row];
            float be = sb[wg][s];
            float al = sa[wg][s];

            float mk = dot16(M, kp);
            unsigned long long cd = dup2(fmaf(be, vi, -al * mk));
#pragma unroll
            for (int j = 0; j < 8; j++) fma2(M[j], cd, kp[j]);
            float o = dot16(M, qp);
            sv[wg][s * 16 + row] = o;
        }
        __syncwarp();
#pragma unroll
        for (int r = 0; r < 8; r++) {
            int f = lane + 32 * r;
            int gg = f >> 7;
            int e = f & 127;
            int grp2 = blockIdx.x * 8 + warp * 2 + gg;
            int rec2 = grp2 >> 4, ch2 = grp2 & 15;
            size_t base4 = ((size_t)rec2 * SEQ_T + ch2 * CH + sub * 32) * 4;
            ((float4*)g_o)[base4 + e] = ((const float4*)sv[warp * 2 + gg])[e];
        }
    }
}

// ---------------- kernel 4: register-tiled output projection ----------------
__global__ __launch_bounds__(256) void final_proj(const float* __restrict__ out_b,
                                                  float* __restrict__ out) {
    extern __shared__ __align__(16) float fsm[];
    float* sw = fsm;                       // [64][192]
    float* so = fsm + 64 * 192;            // [64][FP_SOW]

    int tid = threadIdx.x;
    int tx = tid & 31;
    int ty = tid >> 5;
    int n = blockIdx.x;
    int t0 = blockIdx.y * FP_TT;
    int b = n >> 4;
    int p = n & 15;

    {
        int rr = tid >> 6;
        int cc = tid & 63;
#pragma unroll
        for (int m = 0; m < 16; m++) {
            int mr = m * 4 + rr;
#pragma unroll
            for (int j = 0; j < 3; j++)
                sw[mr * 192 + cc + 64 * j] = g_wtr[mr * 192 + cc + 64 * j];
        }
    }
#pragma unroll
    for (int r = 0; r < 16; r++) {
        int e = tid + 256 * r;
        int i = e & 15;
        int tt = (e >> 4) & 63;
        int h = e >> 10;
        so[(h * 16 + i) * FP_SOW + tt] =
            g_o[((size_t)(n * NH + h) * SEQ_T + t0 + tt) * DH + i];
    }
    __syncthreads();

    unsigned long long acc[8][3];
#pragma unroll
    for (int t = 0; t < 8; t++)
#pragma unroll
        for (int kp = 0; kp < 3; kp++) acc[t][kp] = 0ull;

#pragma unroll 4
    for (int m = 0; m < 64; m++) {
        const unsigned long long* wp = (const unsigned long long*)(sw + m * 192 + tx * 6);
        unsigned long long w0 = wp[0], w1 = wp[1], w2 = wp[2];
        const float* sop = so + m * FP_SOW + ty * 8;
#pragma unroll
        for (int t = 0; t < 8; t++) {
            unsigned long long sd = dup2(sop[t]);
            fma2(acc[t][0], sd, w0);
            fma2(acc[t][1], sd, w1);
            fma2(acc[t][2], sd, w2);
        }
    }

    float2 bias[3];
#pragma unroll
    for (int j = 0; j < 3; j++)
        bias[j] = *(const float2*)(out_b + tx * 6 + 2 * j);
#pragma unroll
    for (int t = 0; t < 8; t++) {
        int tt = t0 + ty * 8 + t;
        float* op = out + (((size_t)b * SEQ_T + tt) * N_P + p) * KOUT + tx * 6;
#pragma unroll
        for (int j = 0; j < 3; j++) {
            float2 v = make_float2(lo32(acc[t][j]) + bias[j].x,
                                   hi32(acc[t][j]) + bias[j].y);
            *(float2*)(op + 2 * j) = v;
        }
    }
}

// ---------------- launch ----------------
extern "C" void kernel_launch(void* const* d_in, const int* in_sizes, int n_in,
                              void* d_out, int out_size) {
    const float* joint  = (const float*)d_in[0];
    const float* curvat = (const float*)d_in[1];
    const float* entrop = (const float*)d_in[2];
    const float* Wq     = (const float*)d_in[3];
    const float* Wk     = (const float*)d_in[4];
    const float* Wv     = (const float*)d_in[5];
    const float* Wbw    = (const float*)d_in[6];
    const float* Wbb    = (const float*)d_in[7];
    const float* Waw    = (const float*)d_in[8];
    const float* Wab    = (const float*)d_in[9];
    const float* curv_w = (const float*)d_in[10];
    const float* ent_w  = (const float*)d_in[11];
    const float* out_w  = (const float*)d_in[12];
    const float* out_b  = (const float*)d_in[13];
    const float* lnqw   = (const float*)d_in[14];
    const float* lnqb   = (const float*)d_in[15];
    const float* lnkw   = (const float*)d_in[16];
    const float* lnkb   = (const float*)d_in[17];
    float* out = (float*)d_out;

    cudaFuncSetAttribute(gemm_tc2, cudaFuncAttributeMaxDynamicSharedMemorySize,
                         GEMM_SMEM);
    cudaFuncSetAttribute(final_proj, cudaFuncAttributeMaxDynamicSharedMemorySize,
                         FP_SMEM);

    constexpr int PACK_TOT = 256 * 128 + KOUT * MEMD;
    pack_all<<<(PACK_TOT + 255) / 256, 256>>>(Wq, Wk, Wv, Wbw, Waw, out_w);
    gemm_tc2<<<dim3(NT / 64, 2), 128, GEMM_SMEM>>>(joint, curvat, entrop, Wbb, Wab,
                                                   curv_w, ent_w, lnqw, lnqb,
                                                   lnkw, lnkb);
    scan_phase1<<<NGRP / 8, 128>>>();
    scan_combine<<<NREC / 8, 128>>>();
    scan_phase3<<<NGRP / 8, 128>>>();
    final_proj<<<dim3(NSEQ, SEQ_T / FP_TT), 256, FP_SMEM>>>(out_b, out);
}